// round 8
// baseline (speedup 1.0000x reference)
#include <cuda_runtime.h>

#define SEQ    16384
#define BATCH   1024
#define NWIN      61
#define STEP     256
#define TPB      128                 // threads per CTA (main)

// Weight table: 8 sets x 256 samples (prefix P[0..3] = sets 0..3,
// suffix S[0..3] = sets 4..7), pre-scaled by 1/61, im = -sin/61.
__device__ float g_Wre[8 * 256];
__device__ float g_Wim[8 * 256];

// ---- Kernel 1: build prefix/suffix weight table (1024 sincosf total) ----
__global__ void table_kernel(const float* __restrict__ freqs) {
    const int p0 = threadIdx.x;                 // 0..255
    const float TWO_PI = 6.283185307179586476925f;
    const float inv = 1.0f / (float)NWIN;
    float cr[4], ci[4];
    #pragma unroll
    for (int k = 0; k < 4; ++k) {
        float sn, cs;
        sincosf(TWO_PI * freqs[p0 + STEP * k], &sn, &cs);
        cr[k] = cs * inv;
        ci[k] = -sn * inv;
    }
    float pr = 0.f, pi = 0.f;
    #pragma unroll
    for (int k = 0; k < 4; ++k) {               // prefixes P[k]
        pr += cr[k]; pi += ci[k];
        g_Wre[k * 256 + p0] = pr;
        g_Wim[k * 256 + p0] = pi;
    }
    float sr = 0.f, si = 0.f;
    #pragma unroll
    for (int k = 3; k >= 0; --k) {              // suffixes S[k]
        sr += cr[k]; si += ci[k];
        g_Wre[(4 + k) * 256 + p0] = sr;
        g_Wim[(4 + k) * 256 + p0] = si;
    }
}

// ---- Kernel 2: one CTA per batch row; whole grid resident in one wave ----
// Thread tid owns float4 groups l = tid + 128g (g=0..31); sample s = 4l+c.
// s mod 256 = 4*(tid&63)+c (g-invariant); wbase = s>>8 = (tid>>6) + 2g.
//   g==0  -> P[q]   g==1 -> P[2+q]   g==30 -> S[q]   g==31 -> S[2+q]
//   g==2..29 -> P[3] (interior full sum; S[0]==P[3] handles wbase=60)
// Edge groups are consumed FIRST so their weights die before the interior
// loop, which then runs with only Ir/Ii live and 7-deep load batches.
__global__ __launch_bounds__(TPB, 8) void welch_kernel(
    const float4* __restrict__ in,
    const float*  __restrict__ fc_w,
    const float*  __restrict__ fc_b,
    float*        __restrict__ out)
{
    const int tid = threadIdx.x;
    const int b   = blockIdx.x;
    const int q   = tid >> 6;        // 0 or 1
    const int j   = tid & 63;        // float4 index within 256-sample period

    const float4* __restrict__ Wre4 = (const float4*)g_Wre;
    const float4* __restrict__ Wim4 = (const float4*)g_Wim;
    const float4* __restrict__ row  = in + (size_t)b * (SEQ / 4) + tid;

    float re0 = 0.f, re1 = 0.f, im0 = 0.f, im1 = 0.f;

    // ---- Edge phase: groups 0, 1, 30, 31 (weights short-lived) ----
    {
        float4 xe0 = __ldcg(row +  0 * TPB);
        float4 xe1 = __ldcg(row +  1 * TPB);
        float4 xe2 = __ldcg(row + 30 * TPB);
        float4 xe3 = __ldcg(row + 31 * TPB);

        float4 Ar = Wre4[(0 + q) * 64 + j], Ai = Wim4[(0 + q) * 64 + j];
        float4 Br = Wre4[(2 + q) * 64 + j], Bi = Wim4[(2 + q) * 64 + j];
        float4 Cr = Wre4[(4 + q) * 64 + j], Ci = Wim4[(4 + q) * 64 + j];
        float4 Dr = Wre4[(6 + q) * 64 + j], Di = Wim4[(6 + q) * 64 + j];

        re0 = fmaf(xe0.x, Ar.x, re0); re0 = fmaf(xe0.y, Ar.y, re0);
        re0 = fmaf(xe0.z, Ar.z, re0); re0 = fmaf(xe0.w, Ar.w, re0);
        im0 = fmaf(xe0.x, Ai.x, im0); im0 = fmaf(xe0.y, Ai.y, im0);
        im0 = fmaf(xe0.z, Ai.z, im0); im0 = fmaf(xe0.w, Ai.w, im0);

        re1 = fmaf(xe1.x, Br.x, re1); re1 = fmaf(xe1.y, Br.y, re1);
        re1 = fmaf(xe1.z, Br.z, re1); re1 = fmaf(xe1.w, Br.w, re1);
        im1 = fmaf(xe1.x, Bi.x, im1); im1 = fmaf(xe1.y, Bi.y, im1);
        im1 = fmaf(xe1.z, Bi.z, im1); im1 = fmaf(xe1.w, Bi.w, im1);

        re0 = fmaf(xe2.x, Cr.x, re0); re0 = fmaf(xe2.y, Cr.y, re0);
        re0 = fmaf(xe2.z, Cr.z, re0); re0 = fmaf(xe2.w, Cr.w, re0);
        im0 = fmaf(xe2.x, Ci.x, im0); im0 = fmaf(xe2.y, Ci.y, im0);
        im0 = fmaf(xe2.z, Ci.z, im0); im0 = fmaf(xe2.w, Ci.w, im0);

        re1 = fmaf(xe3.x, Dr.x, re1); re1 = fmaf(xe3.y, Dr.y, re1);
        re1 = fmaf(xe3.z, Dr.z, re1); re1 = fmaf(xe3.w, Dr.w, re1);
        im1 = fmaf(xe3.x, Di.x, im1); im1 = fmaf(xe3.y, Di.y, im1);
        im1 = fmaf(xe3.z, Di.z, im1); im1 = fmaf(xe3.w, Di.w, im1);
    }

    // ---- Interior phase: groups 2..29, shared weight, 7-deep batches ----
    const float4 Ir = Wre4[3 * 64 + j];
    const float4 Ii = Wim4[3 * 64 + j];

    #pragma unroll
    for (int bt = 0; bt < 4; ++bt) {
        float4 x[7];
        #pragma unroll
        for (int i = 0; i < 7; ++i)
            x[i] = __ldcg(row + (2 + 7 * bt + i) * TPB);

        #pragma unroll
        for (int i = 0; i < 7; ++i) {
            if (i & 1) {
                re1 = fmaf(x[i].x, Ir.x, re1); re1 = fmaf(x[i].y, Ir.y, re1);
                re1 = fmaf(x[i].z, Ir.z, re1); re1 = fmaf(x[i].w, Ir.w, re1);
                im1 = fmaf(x[i].x, Ii.x, im1); im1 = fmaf(x[i].y, Ii.y, im1);
                im1 = fmaf(x[i].z, Ii.z, im1); im1 = fmaf(x[i].w, Ii.w, im1);
            } else {
                re0 = fmaf(x[i].x, Ir.x, re0); re0 = fmaf(x[i].y, Ir.y, re0);
                re0 = fmaf(x[i].z, Ir.z, re0); re0 = fmaf(x[i].w, Ir.w, re0);
                im0 = fmaf(x[i].x, Ii.x, im0); im0 = fmaf(x[i].y, Ii.y, im0);
                im0 = fmaf(x[i].z, Ii.z, im0); im0 = fmaf(x[i].w, Ii.w, im0);
            }
        }
    }

    float re = re0 + re1;
    float im = im0 + im1;

    // Block reduce: 4 warps -> 1 value.
    #pragma unroll
    for (int off = 16; off > 0; off >>= 1) {
        re += __shfl_xor_sync(0xffffffffu, re, off);
        im += __shfl_xor_sync(0xffffffffu, im, off);
    }
    __shared__ float s[8];
    const int w    = tid >> 5;
    const int lane = tid & 31;
    if (lane == 0) { s[w] = re; s[4 + w] = im; }
    __syncthreads();

    if (tid == 0) {
        float fr = (s[0] + s[1]) + (s[2] + s[3]);
        float fi = (s[4] + s[5]) + (s[6] + s[7]);
        float psd = fr * fr + fi * fi;
        out[b] = fmaf(psd, fc_w[0], fc_b[0]);
    }
}

extern "C" void kernel_launch(void* const* d_in, const int* in_sizes, int n_in,
                              void* d_out, int out_size) {
    const float* input = (const float*)d_in[0];   // (1024, 16384) f32
    const float* freqs = (const float*)d_in[1];   // (1024,) f32
    const float* fc_w  = (const float*)d_in[2];   // (1,1) f32
    const float* fc_b  = (const float*)d_in[3];   // (1,) f32
    float* out = (float*)d_out;                   // (1024, 1) f32

    table_kernel<<<1, 256>>>(freqs);
    welch_kernel<<<BATCH, TPB>>>((const float4*)input, fc_w, fc_b, out);
}